// round 17
// baseline (speedup 1.0000x reference)
#include <cuda_runtime.h>
#include <cuda_bf16.h>
#include <cstdint>

// Problem shape (fixed by the reference)
#define BB 8
#define CC 16
#define HH 512
#define WW 1024

// FINAL (converged) — measured optimum, reproduced 3x (ncu 90.5/91.0/91.2us,
// 5.6TB/s DRAM, wall 95.2-96.4us). One thread = 4 consecutive-w pixels;
// disp/index/weight computed once, shared across all 16 channels; per
// channel-iter: 8 batched scalar gathers (default caching) + one aligned
// float4 store. Full falsification ledger:
//   occupancy 46->87%        (R5/R9)  flat
//   L1 wavefronts 67->38%    (R9)     worse (-8us)
//   L2 streaming .cs hints   (R7)     worse (-20us, kills x0/x1 line reuse)
//   smem-staged pure stream  (R10)    flat (request shape not the limiter)
//   8 px/thread              (R13)    worse (-28us, L1 wf explosion + spills)
//   gather batching          (R11/14) neutral
// Traffic is within 8% of the 554MB analytic floor; 5.6TB/s is the chip's
// practical ceiling for this 1:1 read:write stream with data-dependent gathers.
__global__ __launch_bounds__(256) void warp_disp_kernel(
    const float* __restrict__ input,   // [B,C,H,W]
    const float* __restrict__ disp,    // [B,1,H,W]
    float* __restrict__ out)           // [B,C,H,W]
{
    const int tid = blockIdx.x * blockDim.x + threadIdx.x;   // 1M threads
    const int w0  = (tid * 4) & (WW - 1);                    // 0..1020, step 4
    const int bh  = tid / (WW / 4);                          // b*H + h
    const int h   = bh & (HH - 1);
    const int b   = bh >> 9;                                 // /HH

    // disp layout [B,1,H,W] == [B*H*W]; aligned float4 load
    const float4 d4 = __ldg((const float4*)(disp + bh * WW + w0));

    int   x0[4], x1[4];
    float wl[4], wr[4];
    const float dvals[4] = {d4.x, d4.y, d4.z, d4.w};
    #pragma unroll
    for (int i = 0; i < 4; ++i) {
        float x = (float)(w0 + i) + dvals[i];
        x = fminf(fmaxf(x, 0.0f), (float)(WW - 1));
        const float x0f = floorf(x);
        const float x1f = fminf(x0f + 1.0f, (float)(WW - 1));
        x0[i] = (int)x0f;
        x1[i] = (int)x1f;
        wl[i] = x1f - x;          // note: NOT 1-wr; both 0 at the right clamp
        wr[i] = x - x0f;
    }

    // All element offsets fit in int32 (64M elements max).
    const int row_base = (b * CC * HH + h) * WW;
    const float* in_row = input + row_base;
    float*      out_row = out   + row_base + w0;
    const int cstride = HH * WW;   // 524288

    #pragma unroll 4
    for (int c = 0; c < CC; ++c) {
        const float* rc = in_row + c * cstride;
        // Batch all 8 gathers ahead of the FMA/store chain (max MLP per iter).
        const float pl0 = __ldg(rc + x0[0]);
        const float pr0 = __ldg(rc + x1[0]);
        const float pl1 = __ldg(rc + x0[1]);
        const float pr1 = __ldg(rc + x1[1]);
        const float pl2 = __ldg(rc + x0[2]);
        const float pr2 = __ldg(rc + x1[2]);
        const float pl3 = __ldg(rc + x0[3]);
        const float pr3 = __ldg(rc + x1[3]);
        float4 r;
        r.x = wl[0] * pl0 + wr[0] * pr0;
        r.y = wl[1] * pl1 + wr[1] * pr1;
        r.z = wl[2] * pl2 + wr[2] * pr2;
        r.w = wl[3] * pl3 + wr[3] * pr3;
        *(float4*)(out_row + c * cstride) = r;
    }
}

extern "C" void kernel_launch(void* const* d_in, const int* in_sizes, int n_in,
                              void* d_out, int out_size) {
    const float* input = (const float*)d_in[0];
    const float* disp  = (const float*)d_in[1];
    float* out = (float*)d_out;

    const int n_threads = BB * HH * (WW / 4);   // 1,048,576
    const int threads = 256;
    warp_disp_kernel<<<n_threads / threads, threads>>>(input, disp, out);
}